// round 15
// baseline (speedup 1.0000x reference)
#include <cuda_runtime.h>
#include <cuda_fp16.h>
#include <math.h>
#include <stdint.h>

#define BB 16
#define SS 2048
#define HH 1024
#define FF 1024
#define MM (BB*SS)   // 32768

// ---------------- device scratch (no runtime allocation allowed) ----------
__device__ __half g_Xh[(size_t)MM*HH];
__device__ __half g_Ch[(size_t)MM*FF];
__device__ __half g_Am[(size_t)MM*FF];
__device__ float  g_P[(size_t)MM*FF];     // A@w2 + attn_bias (fp32)
__device__ __half g_WCh[(size_t)FF*HH];
__device__ __half g_WAh[(size_t)FF*HH];
__device__ __half g_W2h[(size_t)FF*FF];
__device__ float g_q[BB*FF];
__device__ float g_t1[BB*FF];
__device__ float g_pre[BB*SS];
__device__ float g_alpha[BB*SS];
__device__ float g_Lpre[BB*SS];

// ---------------------------------------------------------------------------
__device__ __forceinline__ void cpa16(uint32_t s, const void* g) {
    asm volatile("cp.async.cg.shared.global [%0], [%1], 16;" :: "r"(s), "l"(g));
}
__device__ __forceinline__ void cp_commit() {
    asm volatile("cp.async.commit_group;");
}
__device__ __forceinline__ void ldsm4(uint32_t* r, uint32_t a) {
    asm volatile("ldmatrix.sync.aligned.m8n8.x4.shared.b16 {%0,%1,%2,%3}, [%4];"
        : "=r"(r[0]), "=r"(r[1]), "=r"(r[2]), "=r"(r[3]) : "r"(a));
}
__device__ __forceinline__ void mma16816(float* c, const uint32_t* a, const uint32_t* b) {
    asm volatile("mma.sync.aligned.m16n8k16.row.col.f32.f16.f16.f32 "
        "{%0,%1,%2,%3}, {%4,%5,%6,%7}, {%8,%9}, {%0,%1,%2,%3};"
        : "+f"(c[0]), "+f"(c[1]), "+f"(c[2]), "+f"(c[3])
        : "r"(a[0]), "r"(a[1]), "r"(a[2]), "r"(a[3]), "r"(b[0]), "r"(b[1]));
}

// ---------------------------------------------------------------------------
__global__ void zero_kernel(float* q, float* h_out, float* pre) {
    int i = blockIdx.x * 256 + threadIdx.x;
    if (i < BB * FF) { q[i] = 0.f; h_out[i] = 0.f; }
    if (i < BB * SS) { pre[i] = 0.f; }
}

// convert X fp32 -> fp16, 1 float4 per thread
__global__ void cvtX_kernel(const float4* __restrict__ X, __half* __restrict__ Xh) {
    size_t i = (size_t)blockIdx.x * 256 + threadIdx.x;
    float4 v = X[i];
    __half2* p = (__half2*)Xh;
    p[i*2]   = __floats2half2_rn(v.x, v.y);
    p[i*2+1] = __floats2half2_rn(v.z, v.w);
}

// transpose + convert weight: T[n][k] = fp16(W[k][n])
__global__ void transW_kernel(const float* __restrict__ W, __half* __restrict__ T) {
    __shared__ float t[32][33];
    int n0 = blockIdx.x * 32, k0 = blockIdx.y * 32;
    int x = threadIdx.x, y = threadIdx.y;   // 32x8
    #pragma unroll
    for (int d = 0; d < 32; d += 8)
        t[y + d][x] = W[(size_t)(k0 + y + d) * FF + n0 + x];
    __syncthreads();
    #pragma unroll
    for (int d = 0; d < 32; d += 8) {
        int n = n0 + y + d, k = k0 + x;
        T[(size_t)n * HH + k] = __float2half(t[x][y + d]);
    }
}

// ---------------------------------------------------------------------------
// HMMA fp16 GEMM:  D[M,N] = A[M,K] @ B^T[N,K]
// CTA tile 128x128x64, 8 warps (4M x 2N), warp tile 32x64, 3-stage cp.async,
// 2 CTAs/SM (<=128 regs, ~111KB smem/CTA). smem rows 144B -> conflict-free ldsm.
// MODE 2: p = sum_n tanh(acc + t1[b,n] + bias[n]) * v[n]; atomicAdd(rowdot[m], p)
// MODE 4: (acc+bias) -> fp32 out (no relu)
// MODE 5: merged C/A: bn<8 -> relu->Ch + q-fusion; bn>=8 -> relu->A fp32+fp16
#define KC 64
#define ROWB 144
#define OFF_A 0
#define OFF_B 18432
#define STAGE_B 36864
#define NSTAGE 3
#define QS_OFF (NSTAGE*STAGE_B)       // 110592
#define SMEM_GEMM (QS_OFF + 512)      // 111104
#define NCHUNK (HH/KC)                // 16

template <int MODE>
__global__ void __launch_bounds__(256, 2)
gemm_mma(const __half* __restrict__ A_g, const __half* __restrict__ B_g,
         const __half* __restrict__ B2_g,
         const float* __restrict__ bias, const float* __restrict__ bias2,
         float* __restrict__ out_f32,
         __half* __restrict__ out_h, __half* __restrict__ out_h2,
         const float* __restrict__ t1, const float* __restrict__ vvec,
         float* __restrict__ rowdot,
         const float* __restrict__ iw, float* __restrict__ q_out)
{
    extern __shared__ char smem[];
    uint32_t sb = (uint32_t)__cvta_generic_to_shared(smem);
    int tid = threadIdx.x, lane = tid & 31, wid = tid >> 5;
    int bn = blockIdx.x, bm = blockIdx.y;

    const bool isA = (MODE == 5) && (bn >= 8);
    const int bnn = (MODE == 5) ? (bn & 7) : bn;

    const __half* Asrc = A_g + (size_t)bm * 128 * HH;
    const __half* Bsel = (MODE == 5 && isA) ? B2_g : B_g;
    const __half* Bsrc = Bsel + (size_t)bnn * 128 * HH;

    int ld_row = tid >> 3;          // 0..31
    int ld_ch  = tid & 7;           // 0..7 (16B chunks of 128B row)

    // prologue: stages 0, 1
    #pragma unroll
    for (int c = 0; c < NSTAGE - 1; c++) {
        uint32_t buf = sb + c * STAGE_B;
        #pragma unroll
        for (int i = 0; i < 4; i++) {
            int row = ld_row + i * 32;
            cpa16(buf + OFF_A + row * ROWB + ld_ch * 16,
                  Asrc + (size_t)row * HH + c * KC + ld_ch * 8);
            cpa16(buf + OFF_B + row * ROWB + ld_ch * 16,
                  Bsrc + (size_t)row * HH + c * KC + ld_ch * 8);
        }
        cp_commit();
    }

    float acc[2][8][4];
    #pragma unroll
    for (int mt = 0; mt < 2; mt++)
        #pragma unroll
        for (int nt = 0; nt < 8; nt++)
            #pragma unroll
            for (int e = 0; e < 4; e++) acc[mt][nt][e] = 0.f;

    int warpM = wid & 3, warpN = wid >> 2;
    int m0 = warpM * 32, n0 = warpN * 64;

    uint32_t a_base = (uint32_t)(m0 + (lane & 15)) * ROWB + (uint32_t)(lane >> 4) * 16;
    int b_rowp = ((lane >> 4) << 3) + (lane & 7);
    uint32_t b_base = (uint32_t)(n0 + b_rowp) * ROWB + (uint32_t)((lane >> 3) & 1) * 16;

    for (int c = 0; c < NCHUNK; c++) {
        if (c < NCHUNK - 2) asm volatile("cp.async.wait_group 1;" ::: "memory");
        else                asm volatile("cp.async.wait_group 0;" ::: "memory");
        __syncthreads();

        if (c + NSTAGE - 1 < NCHUNK) {
            uint32_t buf = sb + ((c + NSTAGE - 1) % NSTAGE) * STAGE_B;
            int kc0 = (c + NSTAGE - 1) * KC;
            #pragma unroll
            for (int i = 0; i < 4; i++) {
                int row = ld_row + i * 32;
                cpa16(buf + OFF_A + row * ROWB + ld_ch * 16,
                      Asrc + (size_t)row * HH + kc0 + ld_ch * 8);
                cpa16(buf + OFF_B + row * ROWB + ld_ch * 16,
                      Bsrc + (size_t)row * HH + kc0 + ld_ch * 8);
            }
        }
        cp_commit();

        uint32_t buf = sb + (c % NSTAGE) * STAGE_B;
        uint32_t As = buf + OFF_A, Bs = buf + OFF_B;

        #pragma unroll
        for (int ks = 0; ks < 4; ks++) {
            uint32_t ah[2][4];
            #pragma unroll
            for (int mt = 0; mt < 2; mt++)
                ldsm4(ah[mt], As + a_base + (uint32_t)mt * (16 * ROWB) + (uint32_t)ks * 32);
            uint32_t bh[8][2];
            #pragma unroll
            for (int p = 0; p < 4; p++) {
                uint32_t r[4];
                ldsm4(r, Bs + b_base + (uint32_t)p * (16 * ROWB) + (uint32_t)ks * 32);
                bh[2*p][0] = r[0]; bh[2*p][1] = r[1];
                bh[2*p+1][0] = r[2]; bh[2*p+1][1] = r[3];
            }
            #pragma unroll
            for (int mt = 0; mt < 2; mt++)
                #pragma unroll
                for (int nt = 0; nt < 8; nt++)
                    mma16816(acc[mt][nt], ah[mt], bh[nt]);
        }
    }

    // ---------------- epilogue ----------------
    int g4 = lane >> 2;           // row-in-8 group
    int cpair = (lane & 3) * 2;   // col pair base

    if (MODE == 2) {
        int batch = bm >> 4;      // 128 rows per bm; 2048 per batch
        #pragma unroll
        for (int mt = 0; mt < 2; mt++) {
            #pragma unroll
            for (int h = 0; h < 2; h++) {
                int grow = bm * 128 + m0 + mt * 16 + g4 + h * 8;
                float p = 0.f;
                #pragma unroll
                for (int nt = 0; nt < 8; nt++) {
                    int n = bnn * 128 + n0 + nt * 8 + cpair;
                    #pragma unroll
                    for (int e = 0; e < 2; e++) {
                        float x = acc[mt][nt][h * 2 + e] + t1[batch * FF + n + e] + bias[n + e];
                        p = fmaf(tanhf(x), vvec[n + e], p);
                    }
                }
                p += __shfl_xor_sync(0xffffffffu, p, 1);
                p += __shfl_xor_sync(0xffffffffu, p, 2);
                if ((lane & 3) == 0) atomicAdd(&rowdot[grow], p);
            }
        }
    } else if (MODE == 4) {
        #pragma unroll
        for (int mt = 0; mt < 2; mt++) {
            #pragma unroll
            for (int h = 0; h < 2; h++) {
                int grow = bm * 128 + m0 + mt * 16 + g4 + h * 8;
                #pragma unroll
                for (int nt = 0; nt < 8; nt++) {
                    int n = bnn * 128 + n0 + nt * 8 + cpair;
                    float v0 = acc[mt][nt][h * 2 + 0] + bias[n + 0];
                    float v1 = acc[mt][nt][h * 2 + 1] + bias[n + 1];
                    *(float2*)(out_f32 + (size_t)grow * FF + n) = make_float2(v0, v1);
                }
            }
        }
    } else {  // MODE 5
        const float* bs = isA ? bias2 : bias;
        #pragma unroll
        for (int mt = 0; mt < 2; mt++) {
            #pragma unroll
            for (int h = 0; h < 2; h++) {
                int grow = bm * 128 + m0 + mt * 16 + g4 + h * 8;
                #pragma unroll
                for (int nt = 0; nt < 8; nt++) {
                    int n = bnn * 128 + n0 + nt * 8 + cpair;
                    float v0 = acc[mt][nt][h * 2 + 0] + bs[n + 0];
                    float v1 = acc[mt][nt][h * 2 + 1] + bs[n + 1];
                    v0 = v0 > 0.f ? v0 : 0.f;
                    v1 = v1 > 0.f ? v1 : 0.f;
                    __half2 hv = __floats2half2_rn(v0, v1);
                    if (isA) {
                        *(float2*)(out_f32 + (size_t)grow * FF + n) = make_float2(v0, v1);
                        *(__half2*)(out_h2 + (size_t)grow * FF + n) = hv;
                    } else {
                        *(__half2*)(out_h + (size_t)grow * FF + n) = hv;
                    }
                }
            }
        }
        if (!isA) {
            // fused q[b,f] += sum_rows relu(acc+bias) * iw[row]
            float* qs_red = (float*)(smem + QS_OFF);
            if (tid < 128) qs_red[tid] = 0.f;
            __syncthreads();
            float iwv[2][2];
            #pragma unroll
            for (int mt = 0; mt < 2; mt++)
                #pragma unroll
                for (int h = 0; h < 2; h++)
                    iwv[mt][h] = iw[bm * 128 + m0 + mt * 16 + g4 + h * 8];
            #pragma unroll
            for (int nt = 0; nt < 8; nt++) {
                #pragma unroll
                for (int e = 0; e < 2; e++) {
                    int n = bnn * 128 + n0 + nt * 8 + cpair + e;
                    float p = 0.f;
                    #pragma unroll
                    for (int mt = 0; mt < 2; mt++)
                        #pragma unroll
                        for (int h = 0; h < 2; h++) {
                            float vv = acc[mt][nt][h * 2 + e] + bias[n];
                            vv = vv > 0.f ? vv : 0.f;
                            p = fmaf(vv, iwv[mt][h], p);
                        }
                    p += __shfl_xor_sync(0xffffffffu, p, 4);
                    p += __shfl_xor_sync(0xffffffffu, p, 8);
                    p += __shfl_xor_sync(0xffffffffu, p, 16);
                    if (g4 == 0)
                        atomicAdd(&qs_red[n0 + nt * 8 + cpair + e], p);
                }
            }
            __syncthreads();
            if (tid < 128)
                atomicAdd(&q_out[(bm >> 4) * FF + bnn * 128 + tid], qs_red[tid]);
        }
    }
}

// ---------------------------------------------------------------------------
// Lpre[m] = sum_n tanh(P[m,n] + t1[b,n]) * v[n]   (one warp per row, P fp32)
__global__ void lpre_epi(const float* __restrict__ P,
                         const float* __restrict__ t1,
                         const float* __restrict__ vvec,
                         float* __restrict__ Lpre)
{
    int m = (blockIdx.x * 256 + threadIdx.x) >> 5;
    int lane = threadIdx.x & 31;
    int b = m >> 11;
    const float4* pp = (const float4*)(P + (size_t)m * FF);
    const float* tb = t1 + b * FF;
    float acc = 0.f;
    #pragma unroll
    for (int k = 0; k < 8; k++) {
        int idx = lane + k * 32;          // float4 index, 0..255
        float4 pv = pp[idx];
        int n = idx * 4;
        acc = fmaf(tanhf(pv.x + tb[n]),     vvec[n],     acc);
        acc = fmaf(tanhf(pv.y + tb[n + 1]), vvec[n + 1], acc);
        acc = fmaf(tanhf(pv.z + tb[n + 2]), vvec[n + 2], acc);
        acc = fmaf(tanhf(pv.w + tb[n + 3]), vvec[n + 3], acc);
    }
    #pragma unroll
    for (int o = 16; o; o >>= 1)
        acc += __shfl_down_sync(0xffffffffu, acc, o);
    if (lane == 0) Lpre[m] = acc;
}

// ---------------------------------------------------------------------------
// out[b,f] += sum_s X[b,s,f] * w[b,s]  — 2 columns per thread via __half2
__global__ void colreduce_h(const __half* __restrict__ Xh,
                            const float* __restrict__ w,
                            float* __restrict__ out)
{
    int f2 = blockIdx.x * 256 + threadIdx.x;   // pair index, 0..511
    int b = blockIdx.y;
    int s0 = blockIdx.z * 128;
    const __half2* hp = (const __half2*)(Xh + ((size_t)b * SS + s0) * FF) + f2;
    const float* wp = w + b * SS + s0;
    float a0 = 0.f, a1 = 0.f;
    #pragma unroll 4
    for (int s = 0; s < 128; s++) {
        float2 cv = __half22float2(hp[(size_t)s * (FF/2)]);
        float ww = wp[s];
        a0 = fmaf(cv.x, ww, a0);
        a1 = fmaf(cv.y, ww, a1);
    }
    atomicAdd(&out[b * FF + f2 * 2], a0);
    atomicAdd(&out[b * FF + f2 * 2 + 1], a1);
}

// t1[b,n] += sum_k q[b,k0+k] * w1[k0+k,n]   (k-split via blockIdx.z, atomic)
__global__ void smallgemm_kernel(const float* __restrict__ q,
                                 const float* __restrict__ w1,
                                 float* __restrict__ t1)
{
    __shared__ float qs[256];
    int n = blockIdx.x * 256 + threadIdx.x;
    int b = blockIdx.y;
    int k0 = blockIdx.z * 256;
    qs[threadIdx.x] = q[b * FF + k0 + threadIdx.x];
    __syncthreads();
    float acc = 0.f;
    #pragma unroll 8
    for (int k = 0; k < 256; k++)
        acc = fmaf(qs[k], w1[(size_t)(k0 + k) * FF + n], acc);
    atomicAdd(&t1[b * FF + n], acc);
}

__global__ void zero_t1(float* t1) {
    t1[blockIdx.x * 256 + threadIdx.x] = 0.f;
}

// ---------------------------------------------------------------------------
__device__ __forceinline__ float blockReduce(float v, bool do_max) {
    __shared__ float sm[32];
    __syncthreads();
    int lane = threadIdx.x & 31, wid = threadIdx.x >> 5;
    #pragma unroll
    for (int o = 16; o; o >>= 1) {
        float t = __shfl_down_sync(0xffffffffu, v, o);
        v = do_max ? fmaxf(v, t) : v + t;
    }
    if (lane == 0) sm[wid] = v;
    __syncthreads();
    int nw = blockDim.x >> 5;
    v = (threadIdx.x < nw) ? sm[threadIdx.x] : (do_max ? -1e30f : 0.f);
    if (wid == 0) {
        #pragma unroll
        for (int o = 16; o; o >>= 1) {
            float t = __shfl_down_sync(0xffffffffu, v, o);
            v = do_max ? fmaxf(v, t) : v + t;
        }
        if (lane == 0) sm[0] = v;
    }
    __syncthreads();
    return sm[0];
}

__global__ void softmax_kernel(const float* __restrict__ pre,
                               const float* __restrict__ mask,
                               float* __restrict__ alpha)
{
    int b = blockIdx.x, tid = threadIdx.x;
    float z[8];
    float mx = -1e30f;
    #pragma unroll
    for (int i = 0; i < 8; i++) {
        int s = tid + i * 256;
        z[i] = pre[b * SS + s] + (1.f - mask[b * SS + s]) * -10000.f;
        mx = fmaxf(mx, z[i]);
    }
    mx = blockReduce(mx, true);
    float sum = 0.f;
    #pragma unroll
    for (int i = 0; i < 8; i++) { z[i] = expf(z[i] - mx); sum += z[i]; }
    sum = blockReduce(sum, false);
    float inv = 1.f / sum;
    #pragma unroll
    for (int i = 0; i < 8; i++)
        alpha[b * SS + tid + i * 256] = z[i] * inv;
}

__global__ void sparsemax_kernel(const float* __restrict__ Lpre,
                                 const float* __restrict__ mask,
                                 const float* __restrict__ w_1,
                                 const float* __restrict__ w_2,
                                 const float* __restrict__ w_3,
                                 const int* __restrict__ layer_i,
                                 float* __restrict__ Lout)
{
    __shared__ float zs[SS];
    __shared__ float cum[SS];
    __shared__ int scnt;
    int b = blockIdx.x, tid = threadIdx.x;

    int li = layer_i[0];
    float a1 = w_1[0], a2 = w_2[0], a3 = w_3[0];
    float x;
    if (li == 0)      x = a3 * a3 - a2 * a2 - a1 * a1;
    else if (li == 1) x = a3 * a3 - a2 * a2;
    else              x = a3 * a3;
    float sig = 1.f / (1.f + expf(-x));

    for (int i = tid; i < SS; i += 1024)
        zs[i] = Lpre[b * SS + i] * sig + (1.f - mask[b * SS + i]) * -10000.f;
    if (tid == 0) scnt = 0;
    __syncthreads();

    for (int k = 2; k <= SS; k <<= 1) {
        for (int j = k >> 1; j > 0; j >>= 1) {
            for (int t = tid; t < SS; t += 1024) {
                int ixj = t ^ j;
                if (ixj > t) {
                    float a = zs[t], c = zs[ixj];
                    bool up = ((t & k) == 0);
                    if ((a > c) == up) { zs[t] = c; zs[ixj] = a; }
                }
            }
            __syncthreads();
        }
    }

    cum[tid]        = zs[SS - 1 - tid];
    cum[tid + 1024] = zs[SS - 1 - (tid + 1024)];
    __syncthreads();
    for (int off = 1; off < SS; off <<= 1) {
        float v0 = (tid >= off) ? cum[tid - off] : 0.f;
        float v1 = cum[tid + 1024 - off];
        __syncthreads();
        cum[tid] += v0;
        cum[tid + 1024] += v1;
        __syncthreads();
    }

    int c = 0;
    #pragma unroll
    for (int r = 0; r < 2; r++) {
        int i = tid + r * 1024;
        if (1.f + (float)(i + 1) * zs[SS - 1 - i] > cum[i]) c++;
    }
    atomicAdd(&scnt, c);
    __syncthreads();
    int ks = scnt;
    float tau = (cum[ks - 1] - 1.f) / (float)ks;

    for (int i = tid; i < SS; i += 1024) {
        float zv = Lpre[b * SS + i] * sig + (1.f - mask[b * SS + i]) * -10000.f;
        Lout[b * SS + i] = fmaxf(zv - tau, 0.f);
    }
}

// ---------------------------------------------------------------------------
extern "C" void kernel_launch(void* const* d_in, const int* in_sizes, int n_in,
                              void* d_out, int out_size)
{
    const float* mask      = (const float*)d_in[0];
    const float* X         = (const float*)d_in[1];
    const float* iw        = (const float*)d_in[2];
    const float* W_C       = (const float*)d_in[3];
    const float* b_C       = (const float*)d_in[4];
    const float* W_A       = (const float*)d_in[5];
    const float* b_A       = (const float*)d_in[6];
    const float* w1        = (const float*)d_in[7];
    const float* w2        = (const float*)d_in[8];
    const float* attn_bias = (const float*)d_in[9];
    const float* v         = (const float*)d_in[10];
    const float* w_1       = (const float*)d_in[11];
    const float* w_2s      = (const float*)d_in[12];
    const float* w_3       = (const float*)d_in[13];
    const int*   layer_i   = (const int*)d_in[14];

    float* out   = (float*)d_out;
    float* h_out = out;
    float* L_out = out + BB * FF;
    float* A_out = out + BB * FF + BB * SS;

    __half *pXh, *pCh, *pAh, *pWCh, *pWAh, *pW2h;
    float *pP, *pq, *pt1, *ppre, *palpha, *pLpre;
    cudaGetSymbolAddress((void**)&pXh, g_Xh);
    cudaGetSymbolAddress((void**)&pCh, g_Ch);
    cudaGetSymbolAddress((void**)&pAh, g_Am);
    cudaGetSymbolAddress((void**)&pP,  g_P);
    cudaGetSymbolAddress((void**)&pWCh, g_WCh);
    cudaGetSymbolAddress((void**)&pWAh, g_WAh);
    cudaGetSymbolAddress((void**)&pW2h, g_W2h);
    cudaGetSymbolAddress((void**)&pq, g_q);
    cudaGetSymbolAddress((void**)&pt1, g_t1);
    cudaGetSymbolAddress((void**)&ppre, g_pre);
    cudaGetSymbolAddress((void**)&palpha, g_alpha);
    cudaGetSymbolAddress((void**)&pLpre, g_Lpre);

    cudaFuncSetAttribute(gemm_mma<2>, cudaFuncAttributeMaxDynamicSharedMemorySize, SMEM_GEMM);
    cudaFuncSetAttribute(gemm_mma<4>, cudaFuncAttributeMaxDynamicSharedMemorySize, SMEM_GEMM);
    cudaFuncSetAttribute(gemm_mma<5>, cudaFuncAttributeMaxDynamicSharedMemorySize, SMEM_GEMM);

    dim3 tgrid(FF / 128, MM / 128);       // (8, 256)
    dim3 cagrid(2 * FF / 128, MM / 128);  // (16, 256) merged C/A
    dim3 wgrid(FF / 32, HH / 32);

    cudaStream_t s2;
    cudaStreamCreateWithFlags(&s2, cudaStreamNonBlocking);
    cudaEvent_t e0, eT, eCA, e2;
    cudaEventCreateWithFlags(&e0, cudaEventDisableTiming);
    cudaEventCreateWithFlags(&eT, cudaEventDisableTiming);
    cudaEventCreateWithFlags(&eCA, cudaEventDisableTiming);
    cudaEventCreateWithFlags(&e2, cudaEventDisableTiming);

    // ---- main: zero + cvtX ; side: transW (overlapped) ----
    zero_kernel<<<128, 256>>>(pq, h_out, ppre);
    cudaEventRecord(e0, 0);
    cudaStreamWaitEvent(s2, e0, 0);
    transW_kernel<<<wgrid, dim3(32, 8), 0, s2>>>(W_C, pWCh);
    transW_kernel<<<wgrid, dim3(32, 8), 0, s2>>>(W_A, pWAh);
    transW_kernel<<<wgrid, dim3(32, 8), 0, s2>>>(w2, pW2h);
    cudaEventRecord(eT, s2);

    cvtX_kernel<<<(MM * HH / 4) / 256, 256>>>((const float4*)X, pXh);
    cudaStreamWaitEvent(0, eT, 0);

    // ---- merged C+A GEMM ----
    gemm_mma<5><<<cagrid, 256, SMEM_GEMM>>>(pXh, pWCh, pWAh, b_C, b_A,
                                            A_out, pCh, pAh,
                                            nullptr, nullptr, nullptr, iw, pq);
    cudaEventRecord(eCA, 0);

    // ---- side: P = A@w2 + attn_bias (fp32), concurrent with alpha chain ----
    cudaStreamWaitEvent(s2, eCA, 0);
    gemm_mma<4><<<tgrid, 256, SMEM_GEMM, s2>>>(pAh, pW2h, nullptr, attn_bias, nullptr,
                                               pP, nullptr, nullptr,
                                               nullptr, nullptr, nullptr, nullptr, nullptr);
    cudaEventRecord(e2, s2);

    // ---- main: alpha chain ----
    zero_t1<<<BB * FF / 256, 256>>>(pt1);
    smallgemm_kernel<<<dim3(FF / 256, BB, 4), 256>>>(pq, w1, pt1);
    gemm_mma<2><<<tgrid, 256, SMEM_GEMM>>>(pCh, pW2h, nullptr, attn_bias, nullptr,
                                           nullptr, nullptr, nullptr,
                                           pt1, v, ppre, nullptr, nullptr);
    softmax_kernel<<<BB, 256>>>(ppre, mask, palpha);
    colreduce_h<<<dim3(FF / 512, BB, 16), 256>>>(pCh, palpha, h_out);
    zero_t1<<<BB * FF / 256, 256>>>(pt1);
    smallgemm_kernel<<<dim3(FF / 256, BB, 4), 256>>>(h_out, w1, pt1);

    // ---- join; Lpre = tanh(P + t1) . v ; sparsemax ----
    cudaStreamWaitEvent(0, e2, 0);
    lpre_epi<<<MM * 32 / 256, 256>>>(pP, pt1, v, pLpre);
    sparsemax_kernel<<<BB, 1024>>>(pLpre, mask, w_1, w_2s, w_3, layer_i, L_out);
}

// round 16
// speedup vs baseline: 1.4378x; 1.4378x over previous
#include <cuda_runtime.h>
#include <cuda_fp16.h>
#include <math.h>
#include <stdint.h>

#define BB 16
#define SS 2048
#define HH 1024
#define FF 1024
#define MM (BB*SS)   // 32768

// ---------------- device scratch (no runtime allocation allowed) ----------
__device__ __half g_Xh[(size_t)MM*HH];
__device__ __half g_Ch[(size_t)MM*FF];
__device__ __half g_Am[(size_t)MM*FF];
__device__ float  g_P[(size_t)MM*FF];     // A@w2 + attn_bias (fp32)
__device__ __half g_WCh[(size_t)FF*HH];
__device__ __half g_WAh[(size_t)FF*HH];
__device__ __half g_W2h[(size_t)FF*FF];
__device__ float g_q[BB*FF];
__device__ float g_t1[BB*FF];
__device__ float g_pre[BB*SS];
__device__ float g_alpha[BB*SS];
__device__ float g_Lpre[BB*SS];

// ---------------------------------------------------------------------------
__device__ __forceinline__ void cpa16(uint32_t s, const void* g) {
    asm volatile("cp.async.cg.shared.global [%0], [%1], 16;" :: "r"(s), "l"(g));
}
__device__ __forceinline__ void cp_commit() {
    asm volatile("cp.async.commit_group;");
}
__device__ __forceinline__ void ldsm4(uint32_t* r, uint32_t a) {
    asm volatile("ldmatrix.sync.aligned.m8n8.x4.shared.b16 {%0,%1,%2,%3}, [%4];"
        : "=r"(r[0]), "=r"(r[1]), "=r"(r[2]), "=r"(r[3]) : "r"(a));
}
__device__ __forceinline__ void mma16816(float* c, const uint32_t* a, const uint32_t* b) {
    asm volatile("mma.sync.aligned.m16n8k16.row.col.f32.f16.f16.f32 "
        "{%0,%1,%2,%3}, {%4,%5,%6,%7}, {%8,%9}, {%0,%1,%2,%3};"
        : "+f"(c[0]), "+f"(c[1]), "+f"(c[2]), "+f"(c[3])
        : "r"(a[0]), "r"(a[1]), "r"(a[2]), "r"(a[3]), "r"(b[0]), "r"(b[1]));
}

// ---------------------------------------------------------------------------
__global__ void zero_kernel(float* q, float* h_out, float* pre) {
    int i = blockIdx.x * 256 + threadIdx.x;
    if (i < BB * FF) { q[i] = 0.f; h_out[i] = 0.f; }
    if (i < BB * SS) { pre[i] = 0.f; }
}

// convert X fp32 -> fp16, 2 float4 in -> 1 uint4 out per thread
__global__ void cvtX_kernel(const float4* __restrict__ X, uint4* __restrict__ Xh) {
    size_t i = (size_t)blockIdx.x * 256 + threadIdx.x;   // over MM*HH/8
    float4 a = X[i * 2], b = X[i * 2 + 1];
    __half2 h0 = __floats2half2_rn(a.x, a.y);
    __half2 h1 = __floats2half2_rn(a.z, a.w);
    __half2 h2 = __floats2half2_rn(b.x, b.y);
    __half2 h3 = __floats2half2_rn(b.z, b.w);
    uint4 o;
    o.x = *(uint32_t*)&h0; o.y = *(uint32_t*)&h1;
    o.z = *(uint32_t*)&h2; o.w = *(uint32_t*)&h3;
    Xh[i] = o;
}

// transpose + convert weight: T[n][k] = fp16(W[k][n])
__global__ void transW_kernel(const float* __restrict__ W, __half* __restrict__ T) {
    __shared__ float t[32][33];
    int n0 = blockIdx.x * 32, k0 = blockIdx.y * 32;
    int x = threadIdx.x, y = threadIdx.y;   // 32x8
    #pragma unroll
    for (int d = 0; d < 32; d += 8)
        t[y + d][x] = W[(size_t)(k0 + y + d) * FF + n0 + x];
    __syncthreads();
    #pragma unroll
    for (int d = 0; d < 32; d += 8) {
        int n = n0 + y + d, k = k0 + x;
        T[(size_t)n * HH + k] = __float2half(t[x][y + d]);
    }
}

// ---------------------------------------------------------------------------
// HMMA fp16 GEMM:  D[M,N] = A[M,K] @ B^T[N,K]
// CTA tile 128x128x32, 8 warps (4M x 2N), warp tile 32x64, 4-stage cp.async,
// 2 CTAs/SM (<=128 regs, 80KB smem). smem row stride 80B -> conflict-free ldsm.
// MODE 2: p = sum_n tanh(acc + t1[b,n] + bias[n]) * v[n]; atomicAdd(rowdot[m], p)
// MODE 4: (acc+bias) -> fp32 out (no relu)
// MODE 5: merged C/A: bn<8 -> relu->Ch + q-fusion; bn>=8 -> relu->A fp32+fp16
#define KC 32
#define ROWB 80
#define OFF_A 0
#define OFF_B 10240
#define STAGE_B 20480
#define NSTAGE 4
#define QS_OFF (NSTAGE*STAGE_B)       // 81920
#define SMEM_GEMM (QS_OFF + 512)      // 82432
#define NCHUNK (HH/KC)                // 32

template <int MODE>
__global__ void __launch_bounds__(256, 2)
gemm_mma(const __half* __restrict__ A_g, const __half* __restrict__ B_g,
         const __half* __restrict__ B2_g,
         const float* __restrict__ bias, const float* __restrict__ bias2,
         float* __restrict__ out_f32,
         __half* __restrict__ out_h, __half* __restrict__ out_h2,
         const float* __restrict__ t1, const float* __restrict__ vvec,
         float* __restrict__ rowdot,
         const float* __restrict__ iw, float* __restrict__ q_out)
{
    extern __shared__ char smem[];
    uint32_t sb = (uint32_t)__cvta_generic_to_shared(smem);
    int tid = threadIdx.x, lane = tid & 31, wid = tid >> 5;
    int bn = blockIdx.x, bm = blockIdx.y;

    const bool isA = (MODE == 5) && (bn >= 8);
    const int bnn = (MODE == 5) ? (bn & 7) : bn;

    const __half* Asrc = A_g + (size_t)bm * 128 * HH;
    const __half* Bsel = (MODE == 5 && isA) ? B2_g : B_g;
    const __half* Bsrc = Bsel + (size_t)bnn * 128 * HH;

    int ld_row = tid >> 2;          // 0..63
    int ld_ch  = tid & 3;           // 0..3 (16B chunks of 64B row)

    // prologue: stages 0..2
    #pragma unroll
    for (int c = 0; c < NSTAGE - 1; c++) {
        uint32_t buf = sb + c * STAGE_B;
        #pragma unroll
        for (int i = 0; i < 2; i++) {
            int row = ld_row + i * 64;
            cpa16(buf + OFF_A + row * ROWB + ld_ch * 16,
                  Asrc + (size_t)row * HH + c * KC + ld_ch * 8);
            cpa16(buf + OFF_B + row * ROWB + ld_ch * 16,
                  Bsrc + (size_t)row * HH + c * KC + ld_ch * 8);
        }
        cp_commit();
    }

    float acc[2][8][4];
    #pragma unroll
    for (int mt = 0; mt < 2; mt++)
        #pragma unroll
        for (int nt = 0; nt < 8; nt++)
            #pragma unroll
            for (int e = 0; e < 4; e++) acc[mt][nt][e] = 0.f;

    int warpM = wid & 3, warpN = wid >> 2;
    int m0 = warpM * 32, n0 = warpN * 64;

    uint32_t a_base = (uint32_t)(m0 + (lane & 15)) * ROWB + (uint32_t)(lane >> 4) * 16;
    int b_rowp = ((lane >> 4) << 3) + (lane & 7);
    uint32_t b_base = (uint32_t)(n0 + b_rowp) * ROWB + (uint32_t)((lane >> 3) & 1) * 16;

    for (int c = 0; c < NCHUNK; c++) {
        asm volatile("cp.async.wait_group 2;" ::: "memory");
        __syncthreads();

        if (c + NSTAGE - 1 < NCHUNK) {
            uint32_t buf = sb + ((c + NSTAGE - 1) % NSTAGE) * STAGE_B;
            int kc0 = (c + NSTAGE - 1) * KC;
            #pragma unroll
            for (int i = 0; i < 2; i++) {
                int row = ld_row + i * 64;
                cpa16(buf + OFF_A + row * ROWB + ld_ch * 16,
                      Asrc + (size_t)row * HH + kc0 + ld_ch * 8);
                cpa16(buf + OFF_B + row * ROWB + ld_ch * 16,
                      Bsrc + (size_t)row * HH + kc0 + ld_ch * 8);
            }
        }
        cp_commit();

        uint32_t buf = sb + (c % NSTAGE) * STAGE_B;
        uint32_t As = buf + OFF_A, Bs = buf + OFF_B;

        #pragma unroll
        for (int ks = 0; ks < 2; ks++) {
            uint32_t ah[2][4];
            #pragma unroll
            for (int mt = 0; mt < 2; mt++)
                ldsm4(ah[mt], As + a_base + (uint32_t)mt * (16 * ROWB) + (uint32_t)ks * 32);
            uint32_t bh[8][2];
            #pragma unroll
            for (int p = 0; p < 4; p++) {
                uint32_t r[4];
                ldsm4(r, Bs + b_base + (uint32_t)p * (16 * ROWB) + (uint32_t)ks * 32);
                bh[2*p][0] = r[0]; bh[2*p][1] = r[1];
                bh[2*p+1][0] = r[2]; bh[2*p+1][1] = r[3];
            }
            #pragma unroll
            for (int mt = 0; mt < 2; mt++)
                #pragma unroll
                for (int nt = 0; nt < 8; nt++)
                    mma16816(acc[mt][nt], ah[mt], bh[nt]);
        }
    }

    // ---------------- epilogue ----------------
    int g4 = lane >> 2;           // row-in-8 group
    int cpair = (lane & 3) * 2;   // col pair base

    if (MODE == 2) {
        int batch = bm >> 4;      // 128 rows per bm; 2048 per batch
        #pragma unroll
        for (int mt = 0; mt < 2; mt++) {
            #pragma unroll
            for (int h = 0; h < 2; h++) {
                int grow = bm * 128 + m0 + mt * 16 + g4 + h * 8;
                float p = 0.f;
                #pragma unroll
                for (int nt = 0; nt < 8; nt++) {
                    int n = bnn * 128 + n0 + nt * 8 + cpair;
                    #pragma unroll
                    for (int e = 0; e < 2; e++) {
                        float x = acc[mt][nt][h * 2 + e] + t1[batch * FF + n + e] + bias[n + e];
                        p = fmaf(tanhf(x), vvec[n + e], p);
                    }
                }
                p += __shfl_xor_sync(0xffffffffu, p, 1);
                p += __shfl_xor_sync(0xffffffffu, p, 2);
                if ((lane & 3) == 0) atomicAdd(&rowdot[grow], p);
            }
        }
    } else if (MODE == 4) {
        #pragma unroll
        for (int mt = 0; mt < 2; mt++) {
            #pragma unroll
            for (int h = 0; h < 2; h++) {
                int grow = bm * 128 + m0 + mt * 16 + g4 + h * 8;
                #pragma unroll
                for (int nt = 0; nt < 8; nt++) {
                    int n = bnn * 128 + n0 + nt * 8 + cpair;
                    float v0 = acc[mt][nt][h * 2 + 0] + bias[n + 0];
                    float v1 = acc[mt][nt][h * 2 + 1] + bias[n + 1];
                    *(float2*)(out_f32 + (size_t)grow * FF + n) = make_float2(v0, v1);
                }
            }
        }
    } else {  // MODE 5
        const float* bs = isA ? bias2 : bias;
        #pragma unroll
        for (int mt = 0; mt < 2; mt++) {
            #pragma unroll
            for (int h = 0; h < 2; h++) {
                int grow = bm * 128 + m0 + mt * 16 + g4 + h * 8;
                #pragma unroll
                for (int nt = 0; nt < 8; nt++) {
                    int n = bnn * 128 + n0 + nt * 8 + cpair;
                    float v0 = acc[mt][nt][h * 2 + 0] + bs[n + 0];
                    float v1 = acc[mt][nt][h * 2 + 1] + bs[n + 1];
                    v0 = v0 > 0.f ? v0 : 0.f;
                    v1 = v1 > 0.f ? v1 : 0.f;
                    __half2 hv = __floats2half2_rn(v0, v1);
                    if (isA) {
                        *(float2*)(out_f32 + (size_t)grow * FF + n) = make_float2(v0, v1);
                        *(__half2*)(out_h2 + (size_t)grow * FF + n) = hv;
                    } else {
                        *(__half2*)(out_h + (size_t)grow * FF + n) = hv;
                    }
                }
            }
        }
        if (!isA) {
            // fused q[b,f] += sum_rows relu(acc+bias) * iw[row]
            float* qs_red = (float*)(smem + QS_OFF);
            if (tid < 128) qs_red[tid] = 0.f;
            __syncthreads();
            float iwv[2][2];
            #pragma unroll
            for (int mt = 0; mt < 2; mt++)
                #pragma unroll
                for (int h = 0; h < 2; h++)
                    iwv[mt][h] = iw[bm * 128 + m0 + mt * 16 + g4 + h * 8];
            #pragma unroll
            for (int nt = 0; nt < 8; nt++) {
                #pragma unroll
                for (int e = 0; e < 2; e++) {
                    int n = bnn * 128 + n0 + nt * 8 + cpair + e;
                    float p = 0.f;
                    #pragma unroll
                    for (int mt = 0; mt < 2; mt++)
                        #pragma unroll
                        for (int h = 0; h < 2; h++) {
                            float vv = acc[mt][nt][h * 2 + e] + bias[n];
                            vv = vv > 0.f ? vv : 0.f;
                            p = fmaf(vv, iwv[mt][h], p);
                        }
                    p += __shfl_xor_sync(0xffffffffu, p, 4);
                    p += __shfl_xor_sync(0xffffffffu, p, 8);
                    p += __shfl_xor_sync(0xffffffffu, p, 16);
                    if (g4 == 0)
                        atomicAdd(&qs_red[n0 + nt * 8 + cpair + e], p);
                }
            }
            __syncthreads();
            if (tid < 128)
                atomicAdd(&q_out[(bm >> 4) * FF + bnn * 128 + tid], qs_red[tid]);
        }
    }
}

// ---------------------------------------------------------------------------
// Lpre[m] = sum_n tanh(P[m,n] + t1[b,n]) * v[n]   (one warp per row, P fp32)
__global__ void lpre_epi(const float* __restrict__ P,
                         const float* __restrict__ t1,
                         const float* __restrict__ vvec,
                         float* __restrict__ Lpre)
{
    int m = (blockIdx.x * 256 + threadIdx.x) >> 5;
    int lane = threadIdx.x & 31;
    int b = m >> 11;
    const float4* pp = (const float4*)(P + (size_t)m * FF);
    const float* tb = t1 + b * FF;
    float acc = 0.f;
    #pragma unroll
    for (int k = 0; k < 8; k++) {
        int idx = lane + k * 32;          // float4 index, 0..255
        float4 pv = pp[idx];
        int n = idx * 4;
        acc = fmaf(tanhf(pv.x + tb[n]),     vvec[n],     acc);
        acc = fmaf(tanhf(pv.y + tb[n + 1]), vvec[n + 1], acc);
        acc = fmaf(tanhf(pv.z + tb[n + 2]), vvec[n + 2], acc);
        acc = fmaf(tanhf(pv.w + tb[n + 3]), vvec[n + 3], acc);
    }
    #pragma unroll
    for (int o = 16; o; o >>= 1)
        acc += __shfl_down_sync(0xffffffffu, acc, o);
    if (lane == 0) Lpre[m] = acc;
}

// ---------------------------------------------------------------------------
// out[b,f] += sum_s X[b,s,f] * w[b,s]  — 2 columns per thread via __half2
__global__ void colreduce_h(const __half* __restrict__ Xh,
                            const float* __restrict__ w,
                            float* __restrict__ out)
{
    int f2 = blockIdx.x * 256 + threadIdx.x;   // pair index, 0..511
    int b = blockIdx.y;
    int s0 = blockIdx.z * 128;
    const __half2* hp = (const __half2*)(Xh + ((size_t)b * SS + s0) * FF) + f2;
    const float* wp = w + b * SS + s0;
    float a0 = 0.f, a1 = 0.f;
    #pragma unroll 4
    for (int s = 0; s < 128; s++) {
        float2 cv = __half22float2(hp[(size_t)s * (FF/2)]);
        float ww = wp[s];
        a0 = fmaf(cv.x, ww, a0);
        a1 = fmaf(cv.y, ww, a1);
    }
    atomicAdd(&out[b * FF + f2 * 2], a0);
    atomicAdd(&out[b * FF + f2 * 2 + 1], a1);
}

// t1[b,n] += sum_k q[b,k0+k] * w1[k0+k,n]   (k-split via blockIdx.z, atomic)
__global__ void smallgemm_kernel(const float* __restrict__ q,
                                 const float* __restrict__ w1,
                                 float* __restrict__ t1)
{
    __shared__ float qs[256];
    int n = blockIdx.x * 256 + threadIdx.x;
    int b = blockIdx.y;
    int k0 = blockIdx.z * 256;
    qs[threadIdx.x] = q[b * FF + k0 + threadIdx.x];
    __syncthreads();
    float acc = 0.f;
    #pragma unroll 8
    for (int k = 0; k < 256; k++)
        acc = fmaf(qs[k], w1[(size_t)(k0 + k) * FF + n], acc);
    atomicAdd(&t1[b * FF + n], acc);
}

__global__ void zero_t1(float* t1) {
    t1[blockIdx.x * 256 + threadIdx.x] = 0.f;
}

// ---------------------------------------------------------------------------
__device__ __forceinline__ float blockReduce(float v, bool do_max) {
    __shared__ float sm[32];
    __syncthreads();
    int lane = threadIdx.x & 31, wid = threadIdx.x >> 5;
    #pragma unroll
    for (int o = 16; o; o >>= 1) {
        float t = __shfl_down_sync(0xffffffffu, v, o);
        v = do_max ? fmaxf(v, t) : v + t;
    }
    if (lane == 0) sm[wid] = v;
    __syncthreads();
    int nw = blockDim.x >> 5;
    v = (threadIdx.x < nw) ? sm[threadIdx.x] : (do_max ? -1e30f : 0.f);
    if (wid == 0) {
        #pragma unroll
        for (int o = 16; o; o >>= 1) {
            float t = __shfl_down_sync(0xffffffffu, v, o);
            v = do_max ? fmaxf(v, t) : v + t;
        }
        if (lane == 0) sm[0] = v;
    }
    __syncthreads();
    return sm[0];
}

__global__ void softmax_kernel(const float* __restrict__ pre,
                               const float* __restrict__ mask,
                               float* __restrict__ alpha)
{
    int b = blockIdx.x, tid = threadIdx.x;
    float z[8];
    float mx = -1e30f;
    #pragma unroll
    for (int i = 0; i < 8; i++) {
        int s = tid + i * 256;
        z[i] = pre[b * SS + s] + (1.f - mask[b * SS + s]) * -10000.f;
        mx = fmaxf(mx, z[i]);
    }
    mx = blockReduce(mx, true);
    float sum = 0.f;
    #pragma unroll
    for (int i = 0; i < 8; i++) { z[i] = expf(z[i] - mx); sum += z[i]; }
    sum = blockReduce(sum, false);
    float inv = 1.f / sum;
    #pragma unroll
    for (int i = 0; i < 8; i++)
        alpha[b * SS + tid + i * 256] = z[i] * inv;
}

__global__ void sparsemax_kernel(const float* __restrict__ Lpre,
                                 const float* __restrict__ mask,
                                 const float* __restrict__ w_1,
                                 const float* __restrict__ w_2,
                                 const float* __restrict__ w_3,
                                 const int* __restrict__ layer_i,
                                 float* __restrict__ Lout)
{
    __shared__ float zs[SS];
    __shared__ float cum[SS];
    __shared__ int scnt;
    int b = blockIdx.x, tid = threadIdx.x;

    int li = layer_i[0];
    float a1 = w_1[0], a2 = w_2[0], a3 = w_3[0];
    float x;
    if (li == 0)      x = a3 * a3 - a2 * a2 - a1 * a1;
    else if (li == 1) x = a3 * a3 - a2 * a2;
    else              x = a3 * a3;
    float sig = 1.f / (1.f + expf(-x));

    for (int i = tid; i < SS; i += 1024)
        zs[i] = Lpre[b * SS + i] * sig + (1.f - mask[b * SS + i]) * -10000.f;
    if (tid == 0) scnt = 0;
    __syncthreads();

    for (int k = 2; k <= SS; k <<= 1) {
        for (int j = k >> 1; j > 0; j >>= 1) {
            for (int t = tid; t < SS; t += 1024) {
                int ixj = t ^ j;
                if (ixj > t) {
                    float a = zs[t], c = zs[ixj];
                    bool up = ((t & k) == 0);
                    if ((a > c) == up) { zs[t] = c; zs[ixj] = a; }
                }
            }
            __syncthreads();
        }
    }

    cum[tid]        = zs[SS - 1 - tid];
    cum[tid + 1024] = zs[SS - 1 - (tid + 1024)];
    __syncthreads();
    for (int off = 1; off < SS; off <<= 1) {
        float v0 = (tid >= off) ? cum[tid - off] : 0.f;
        float v1 = cum[tid + 1024 - off];
        __syncthreads();
        cum[tid] += v0;
        cum[tid + 1024] += v1;
        __syncthreads();
    }

    int c = 0;
    #pragma unroll
    for (int r = 0; r < 2; r++) {
        int i = tid + r * 1024;
        if (1.f + (float)(i + 1) * zs[SS - 1 - i] > cum[i]) c++;
    }
    atomicAdd(&scnt, c);
    __syncthreads();
    int ks = scnt;
    float tau = (cum[ks - 1] - 1.f) / (float)ks;

    for (int i = tid; i < SS; i += 1024) {
        float zv = Lpre[b * SS + i] * sig + (1.f - mask[b * SS + i]) * -10000.f;
        Lout[b * SS + i] = fmaxf(zv - tau, 0.f);
    }
}

// ---------------------------------------------------------------------------
extern "C" void kernel_launch(void* const* d_in, const int* in_sizes, int n_in,
                              void* d_out, int out_size)
{
    const float* mask      = (const float*)d_in[0];
    const float* X         = (const float*)d_in[1];
    const float* iw        = (const float*)d_in[2];
    const float* W_C       = (const float*)d_in[3];
    const float* b_C       = (const float*)d_in[4];
    const float* W_A       = (const float*)d_in[5];
    const float* b_A       = (const float*)d_in[6];
    const float* w1        = (const float*)d_in[7];
    const float* w2        = (const float*)d_in[8];
    const float* attn_bias = (const float*)d_in[9];
    const float* v         = (const float*)d_in[10];
    const float* w_1       = (const float*)d_in[11];
    const float* w_2s      = (const float*)d_in[12];
    const float* w_3       = (const float*)d_in[13];
    const int*   layer_i   = (const int*)d_in[14];

    float* out   = (float*)d_out;
    float* h_out = out;
    float* L_out = out + BB * FF;
    float* A_out = out + BB * FF + BB * SS;

    __half *pXh, *pCh, *pAh, *pWCh, *pWAh, *pW2h;
    float *pP, *pq, *pt1, *ppre, *palpha, *pLpre;
    cudaGetSymbolAddress((void**)&pXh, g_Xh);
    cudaGetSymbolAddress((void**)&pCh, g_Ch);
    cudaGetSymbolAddress((void**)&pAh, g_Am);
    cudaGetSymbolAddress((void**)&pP,  g_P);
    cudaGetSymbolAddress((void**)&pWCh, g_WCh);
    cudaGetSymbolAddress((void**)&pWAh, g_WAh);
    cudaGetSymbolAddress((void**)&pW2h, g_W2h);
    cudaGetSymbolAddress((void**)&pq, g_q);
    cudaGetSymbolAddress((void**)&pt1, g_t1);
    cudaGetSymbolAddress((void**)&ppre, g_pre);
    cudaGetSymbolAddress((void**)&palpha, g_alpha);
    cudaGetSymbolAddress((void**)&pLpre, g_Lpre);

    cudaFuncSetAttribute(gemm_mma<2>, cudaFuncAttributeMaxDynamicSharedMemorySize, SMEM_GEMM);
    cudaFuncSetAttribute(gemm_mma<4>, cudaFuncAttributeMaxDynamicSharedMemorySize, SMEM_GEMM);
    cudaFuncSetAttribute(gemm_mma<5>, cudaFuncAttributeMaxDynamicSharedMemorySize, SMEM_GEMM);

    dim3 tgrid(FF / 128, MM / 128);       // (8, 256)
    dim3 cagrid(2 * FF / 128, MM / 128);  // (16, 256) merged C/A
    dim3 wgrid(FF / 32, HH / 32);

    cudaStream_t s2;
    cudaStreamCreateWithFlags(&s2, cudaStreamNonBlocking);
    cudaEvent_t e0, eT, eCA, e2;
    cudaEventCreateWithFlags(&e0, cudaEventDisableTiming);
    cudaEventCreateWithFlags(&eT, cudaEventDisableTiming);
    cudaEventCreateWithFlags(&eCA, cudaEventDisableTiming);
    cudaEventCreateWithFlags(&e2, cudaEventDisableTiming);

    // ---- main: zero + cvtX ; side: transW (overlapped) ----
    zero_kernel<<<128, 256>>>(pq, h_out, ppre);
    cudaEventRecord(e0, 0);
    cudaStreamWaitEvent(s2, e0, 0);
    transW_kernel<<<wgrid, dim3(32, 8), 0, s2>>>(W_C, pWCh);
    transW_kernel<<<wgrid, dim3(32, 8), 0, s2>>>(W_A, pWAh);
    transW_kernel<<<wgrid, dim3(32, 8), 0, s2>>>(w2, pW2h);
    cudaEventRecord(eT, s2);

    cvtX_kernel<<<(MM * HH / 8) / 256, 256>>>((const float4*)X, (uint4*)pXh);
    cudaStreamWaitEvent(0, eT, 0);

    // ---- merged C+A GEMM ----
    gemm_mma<5><<<cagrid, 256, SMEM_GEMM>>>(pXh, pWCh, pWAh, b_C, b_A,
                                            A_out, pCh, pAh,
                                            nullptr, nullptr, nullptr, iw, pq);
    cudaEventRecord(eCA, 0);

    // ---- side: P = A@w2 + attn_bias (fp32), concurrent with alpha chain ----
    cudaStreamWaitEvent(s2, eCA, 0);
    gemm_mma<4><<<tgrid, 256, SMEM_GEMM, s2>>>(pAh, pW2h, nullptr, attn_bias, nullptr,
                                               pP, nullptr, nullptr,
                                               nullptr, nullptr, nullptr, nullptr, nullptr);
    cudaEventRecord(e2, s2);

    // ---- main: alpha chain ----
    zero_t1<<<BB * FF / 256, 256>>>(pt1);
    smallgemm_kernel<<<dim3(FF / 256, BB, 4), 256>>>(pq, w1, pt1);
    gemm_mma<2><<<tgrid, 256, SMEM_GEMM>>>(pCh, pW2h, nullptr, attn_bias, nullptr,
                                           nullptr, nullptr, nullptr,
                                           pt1, v, ppre, nullptr, nullptr);
    softmax_kernel<<<BB, 256>>>(ppre, mask, palpha);
    colreduce_h<<<dim3(FF / 512, BB, 16), 256>>>(pCh, palpha, h_out);
    zero_t1<<<BB * FF / 256, 256>>>(pt1);
    smallgemm_kernel<<<dim3(FF / 256, BB, 4), 256>>>(h_out, w1, pt1);

    // ---- join; Lpre = tanh(P + t1) . v ; sparsemax ----
    cudaStreamWaitEvent(0, e2, 0);
    lpre_epi<<<MM * 32 / 256, 256>>>(pP, pt1, v, pLpre);
    sparsemax_kernel<<<BB, 1024>>>(pLpre, mask, w_1, w_2s, w_3, layer_i, L_out);
}